// round 10
// baseline (speedup 1.0000x reference)
#include <cuda_runtime.h>
#include <cuda_fp16.h>
#include <cstdint>

// ---------------------------------------------------------------------------
// Scratch (device globals; allocation-free per harness rules)
// ---------------------------------------------------------------------------
#define MROWS 16384   // B*n = 8*2048

__device__ __half g_H1 [MROWS * 512];   // relu(x1@W1+b1)
__device__ __half g_H2 [MROWS * 512];   // relu(x2@W1+b1)
__device__ __half g_QH [MROWS * 512];
__device__ __half g_KH [MROWS * 512];
__device__ __half g_VH [MROWS * 512];
__device__ __half g_O  [MROWS * 512];
__device__ __half g_x1h[MROWS * 128];
__device__ __half g_x2h[MROWS * 128];
__device__ __half g_rh [MROWS * 512];
__device__ __half g_W1t[512 * 128];     // W1^T -> [N=512][K=128]
__device__ __half g_W2h[512 * 512];     // W2 direct [c][d] fp16
__device__ __half g_Wqh[512 * 512];     // Wq flat [j][d]
__device__ __half g_Wkh[512 * 512];
__device__ __half g_Wvh[512 * 512];
__device__ __half g_Wot[512 * 512];     // [n=d][k=h*64+e] gathered from Wo
__device__ __half g_Wqc[512 * 512];     // Wq@W2^T  [j][c]
__device__ __half g_Wkc[512 * 512];     // Wk@W2^T  [j][c]
__device__ float  g_bq [512];           // Wq@b2
__device__ float  g_bk [512];           // Wk@b2
__device__ float  g_zb [512];           // zeros (VH bias)

// ---------------------------------------------------------------------------
// Helpers
// ---------------------------------------------------------------------------
__device__ __forceinline__ uint32_t smem_u32(const void* p) {
    uint32_t a;
    asm("{ .reg .u64 t; cvta.to.shared.u64 t, %1; cvt.u32.u64 %0, t; }" : "=r"(a) : "l"(p));
    return a;
}
__device__ __forceinline__ uint32_t sw128(uint32_t o) { return o ^ ((o >> 3) & 0x70); }

__device__ __forceinline__ void cp_async16(uint32_t dst, const void* src) {
    asm volatile("cp.async.cg.shared.global [%0], [%1], 16;" :: "r"(dst), "l"(src) : "memory");
}
__device__ __forceinline__ void cp_commit() {
    asm volatile("cp.async.commit_group;" ::: "memory");
}
template<int N> __device__ __forceinline__ void cp_wait() {
    asm volatile("cp.async.wait_group %0;" :: "n"(N) : "memory");
}

__device__ __forceinline__ void ldmx4(uint32_t* r, uint32_t addr) {
    asm volatile("ldmatrix.sync.aligned.m8n8.x4.shared.b16 {%0,%1,%2,%3}, [%4];"
                 : "=r"(r[0]), "=r"(r[1]), "=r"(r[2]), "=r"(r[3]) : "r"(addr));
}
__device__ __forceinline__ void ldmx4t(uint32_t* r, uint32_t addr) {
    asm volatile("ldmatrix.sync.aligned.m8n8.x4.trans.shared.b16 {%0,%1,%2,%3}, [%4];"
                 : "=r"(r[0]), "=r"(r[1]), "=r"(r[2]), "=r"(r[3]) : "r"(addr));
}
__device__ __forceinline__ void mma16(float* c, const uint32_t* a, const uint32_t* b) {
    asm volatile(
        "mma.sync.aligned.m16n8k16.row.col.f32.f16.f16.f32 "
        "{%0,%1,%2,%3}, {%4,%5,%6,%7}, {%8,%9}, {%0,%1,%2,%3};"
        : "+f"(c[0]), "+f"(c[1]), "+f"(c[2]), "+f"(c[3])
        : "r"(a[0]), "r"(a[1]), "r"(a[2]), "r"(a[3]), "r"(b[0]), "r"(b[1]));
}
__device__ __forceinline__ uint32_t packh2(float a, float b) {
    __half2 h = __floats2half2_rn(a, b);
    return *(uint32_t*)&h;
}
__device__ __forceinline__ uint32_t h2exp2(uint32_t x) {
    uint32_t y;
    asm("ex2.approx.f16x2 %0, %1;" : "=r"(y) : "r"(x));
    return y;
}
__device__ __forceinline__ float2 h2tof2(uint32_t x) {
    __half2 h = *(__half2*)&x;
    return __half22float2(h);
}
__device__ __forceinline__ uint32_t hadd2(uint32_t a, uint32_t b) {
    uint32_t d;
    asm("add.f16x2 %0, %1, %2;" : "=r"(d) : "r"(a), "r"(b));
    return d;
}

// ---------------------------------------------------------------------------
// Pre-pass kernels
// ---------------------------------------------------------------------------
__global__ void prep_inputs(const float4* __restrict__ x1, const float4* __restrict__ x2,
                            const float4* __restrict__ r,
                            uint4* __restrict__ x1h, uint4* __restrict__ x2h,
                            uint4* __restrict__ rh)
{
    const int z = blockIdx.z;
    const float4* S = (z == 0) ? x1 : (z == 1) ? x2 : r;
    uint4* D = (z == 0) ? x1h : (z == 1) ? x2h : rh;
    const int n8 = (z == 2) ? (MROWS * 512 / 8) : (MROWS * 128 / 8);
    for (int i = blockIdx.x * 256 + threadIdx.x; i < n8; i += 262144) {
        float4 a = S[2 * i], b = S[2 * i + 1];
        uint4 u;
        u.x = packh2(a.x, a.y); u.y = packh2(a.z, a.w);
        u.z = packh2(b.x, b.y); u.w = packh2(b.z, b.w);
        D[i] = u;
    }
}
__global__ void prep_weights(const float* __restrict__ W1, const float* __restrict__ W2,
                             const float* __restrict__ Wq, const float* __restrict__ Wk,
                             const float* __restrict__ Wv, const float* __restrict__ Wo,
                             __half* __restrict__ W1t, __half* __restrict__ W2h,
                             __half* __restrict__ Wqh, __half* __restrict__ Wkh,
                             __half* __restrict__ Wvh, __half* __restrict__ Wot)
{
    const int z = blockIdx.z;
    const int t0 = blockIdx.x * 256 + threadIdx.x;
    if (z == 0) { for (int i = t0; i < 262144; i += 32768) Wqh[i] = __float2half(Wq[i]); }
    else if (z == 1) { for (int i = t0; i < 262144; i += 32768) Wkh[i] = __float2half(Wk[i]); }
    else if (z == 2) { for (int i = t0; i < 262144; i += 32768) Wvh[i] = __float2half(Wv[i]); }
    else if (z == 3) {
        for (int i = t0; i < 262144; i += 32768) {
            int n = i >> 9, k = i & 511, h = k >> 6, e = k & 63;
            Wot[i] = __float2half(Wo[((size_t)h * 512 + n) * 64 + e]);
        }
    } else if (z == 4) {
        for (int i = t0; i < 65536; i += 32768) {
            int n = i >> 7, k = i & 127;
            W1t[i] = __float2half(W1[(size_t)k * 512 + n]);
        }
    } else {
        for (int i = t0; i < 262144; i += 32768) W2h[i] = __float2half(W2[i]);
    }
}
// bq = Wq @ b2, bk = Wk @ b2  (f32-exact; grid 2, block 512)
__global__ void bias_comp(const float* __restrict__ Wq, const float* __restrict__ Wk,
                          const float* __restrict__ b2,
                          float* __restrict__ bq, float* __restrict__ bk)
{
    const float* W = (blockIdx.x == 0) ? Wq : Wk;
    float* o = (blockIdx.x == 0) ? bq : bk;
    int j = threadIdx.x;
    float s = 0.f;
    for (int d = 0; d < 512; d++) s += W[(size_t)j * 512 + d] * b2[d];
    o[j] = s;
}

// ---------------------------------------------------------------------------
// Batched fp16 GEMM: C[M,N] = act(A[M,K] @ B^T + bias_z), z selects (A,B,C,bias)
// CTA tile 128x128x64, 256 threads, warp tile 32x64, 3-stage cp.async.
// ---------------------------------------------------------------------------
#define GSTAGE 32768
#define GEMM_SMEM (3 * GSTAGE)

template<bool RELU, bool BIAS, bool OUTF32>
__global__ __launch_bounds__(256, 2)
void gemm_hb(const __half* __restrict__ A0, const __half* __restrict__ A1, const __half* __restrict__ A2,
             const __half* __restrict__ B0, const __half* __restrict__ B1, const __half* __restrict__ B2,
             const float* __restrict__ bias0, const float* __restrict__ bias1, const float* __restrict__ bias2,
             void* __restrict__ C0, void* __restrict__ C1, void* __restrict__ C2,
             int K, int ldc)
{
    const int z = blockIdx.z;
    const __half* A = (z == 0) ? A0 : (z == 1) ? A1 : A2;
    const __half* B = (z == 0) ? B0 : (z == 1) ? B1 : B2;
    const float* bias = (z == 0) ? bias0 : (z == 1) ? bias1 : bias2;
    void* Cout = (z == 0) ? C0 : (z == 1) ? C1 : C2;

    extern __shared__ char smem[];
    const uint32_t sb = smem_u32(smem);
    const int tid = threadIdx.x, w = tid >> 5, lane = tid & 31;
    const int qr = lane >> 2, qc = lane & 3;
    const int m0 = blockIdx.y * 128, n0 = blockIdx.x * 128;
    const int wm = (w & 3) * 32, wn = (w >> 2) * 64;
    const int T = K >> 6;

    auto load_tile = [&](int t, int s) {
        uint32_t ab = sb + (uint32_t)s * GSTAGE, bb = ab + 16384;
        int k0 = t << 6;
#pragma unroll
        for (int i = 0; i < 4; i++) {
            int u = tid + i * 256;
            int row = u >> 3, cu = u & 7;
            uint32_t sw = sw128((uint32_t)(row << 7) + (uint32_t)(cu << 4));
            cp_async16(ab + sw, A + (size_t)(m0 + row) * K + k0 + cu * 8);
            cp_async16(bb + sw, B + (size_t)(n0 + row) * K + k0 + cu * 8);
        }
    };

    float acc[2][8][4];
#pragma unroll
    for (int mt = 0; mt < 2; mt++)
#pragma unroll
        for (int nt = 0; nt < 8; nt++)
#pragma unroll
            for (int j = 0; j < 4; j++) acc[mt][nt][j] = 0.f;

    load_tile(0, 0);
    cp_commit();
    if (T > 1) { load_tile(1, 1); cp_commit(); }

    int buf = 0;
    for (int t = 0; t < T; t++) {
        if (t + 1 < T) cp_wait<1>(); else cp_wait<0>();
        __syncthreads();
        if (t + 2 < T) {
            int nb = buf + 2; if (nb >= 3) nb -= 3;
            load_tile(t + 2, nb);
            cp_commit();
        }
        uint32_t ab = sb + (uint32_t)buf * GSTAGE, bb = ab + 16384;
#pragma unroll
        for (int j = 0; j < 4; j++) {
            uint32_t af[2][4], bf[8][2];
#pragma unroll
            for (int mt = 0; mt < 2; mt++) {
                int row = wm + mt * 16 + (lane & 7) + ((lane >> 3) & 1) * 8;
                int unit = 2 * j + (lane >> 4);
                ldmx4(af[mt], ab + sw128((uint32_t)(row << 7) + (uint32_t)(unit << 4)));
            }
#pragma unroll
            for (int p = 0; p < 4; p++) {
                uint32_t r[4];
                int row = wn + p * 16 + (lane & 7) + ((lane >> 4) & 1) * 8;
                int unit = 2 * j + ((lane >> 3) & 1);
                ldmx4(r, bb + sw128((uint32_t)(row << 7) + (uint32_t)(unit << 4)));
                bf[2 * p][0] = r[0]; bf[2 * p][1] = r[1];
                bf[2 * p + 1][0] = r[2]; bf[2 * p + 1][1] = r[3];
            }
#pragma unroll
            for (int mt = 0; mt < 2; mt++)
#pragma unroll
                for (int nt = 0; nt < 8; nt++)
                    mma16(acc[mt][nt], af[mt], bf[nt]);
        }
        if (++buf == 3) buf = 0;
    }

#pragma unroll
    for (int mt = 0; mt < 2; mt++) {
#pragma unroll
        for (int nt = 0; nt < 8; nt++) {
            int row = m0 + wm + mt * 16 + qr;
            int col = n0 + wn + nt * 8 + qc * 2;
            float b0 = BIAS ? bias[col] : 0.f;
            float b1 = BIAS ? bias[col + 1] : 0.f;
            float v0 = acc[mt][nt][0] + b0, v1 = acc[mt][nt][1] + b1;
            float v2 = acc[mt][nt][2] + b0, v3 = acc[mt][nt][3] + b1;
            if (RELU) {
                v0 = fmaxf(v0, 0.f); v1 = fmaxf(v1, 0.f);
                v2 = fmaxf(v2, 0.f); v3 = fmaxf(v3, 0.f);
            }
            if (OUTF32) {
                float* C = (float*)Cout;
                *(float2*)(C + (size_t)row * ldc + col)       = make_float2(v0, v1);
                *(float2*)(C + (size_t)(row + 8) * ldc + col) = make_float2(v2, v3);
            } else {
                __half* C = (__half*)Cout;
                *(uint32_t*)(C + (size_t)row * ldc + col)       = packh2(v0, v1);
                *(uint32_t*)(C + (size_t)(row + 8) * ldc + col) = packh2(v2, v3);
            }
        }
    }
}

// ---------------------------------------------------------------------------
// Flash attention: grid (16,64), 128-thread CTA, 4 warps x 32 q-rows;
// f16x2 exp; P in registers; 3-stage KV pipeline; HADD2-tree row sums.
// smem 64KB; min 3 CTAs/SM (192KB smem, regs clamped to 170).
// ---------------------------------------------------------------------------
#define FL_SMEM (16384 + 3 * 16384)

__global__ __launch_bounds__(128, 3)
void flash_h(const __half* __restrict__ QH, const __half* __restrict__ KH,
             const __half* __restrict__ VH, __half* __restrict__ O)
{
    extern __shared__ char smc[];
    const uint32_t sb = smem_u32(smc);
    const int tid  = threadIdx.x;
    const int w    = tid >> 5;
    const int lane = tid & 31;
    const int qr   = lane >> 2;
    const int qc   = lane & 3;
    const float c2 = 0.18033688011112042f;   // 0.125 * log2(e)

    const int m0 = blockIdx.x * 128;
    const int bh = blockIdx.y;
    const size_t base = (size_t)(bh >> 3) * 2048 * 512 + (size_t)(bh & 7) * 64;

    {
        const __half* Qg = QH + base + (size_t)m0 * 512;
#pragma unroll
        for (int i = 0; i < 8; i++) {
            int u = tid + i * 128;
            int row = u >> 3, cu = u & 7;
            cp_async16(sb + sw128((uint32_t)(row << 7) + (uint32_t)(cu << 4)),
                       Qg + (size_t)row * 512 + cu * 8);
        }
        cp_commit();
    }
    auto load_kv = [&](int it, int s) {
        uint32_t kb = sb + 16384u + (uint32_t)s * 16384u;
        uint32_t vb = kb + 8192u;
        const __half* Kg = KH + base + (size_t)(it * 64) * 512;
        const __half* Vg = VH + base + (size_t)(it * 64) * 512;
#pragma unroll
        for (int i = 0; i < 4; i++) {
            int u = tid + i * 128;
            int row = u >> 3, cu = u & 7;
            uint32_t sw = sw128((uint32_t)(row << 7) + (uint32_t)(cu << 4));
            cp_async16(kb + sw, Kg + (size_t)row * 512 + cu * 8);
            cp_async16(vb + sw, Vg + (size_t)row * 512 + cu * 8);
        }
    };
    load_kv(0, 0);
    cp_commit();
    load_kv(1, 1);
    cp_commit();

    cp_wait<2>();
    __syncthreads();

    uint32_t aQ[2][4][4];
#pragma unroll
    for (int mt = 0; mt < 2; mt++)
#pragma unroll
        for (int j = 0; j < 4; j++) {
            int row = w * 32 + mt * 16 + (lane & 7) + ((lane >> 3) & 1) * 8;
            int unit = 2 * j + (lane >> 4);
            ldmx4(aQ[mt][j], sb + sw128((uint32_t)(row << 7) + (uint32_t)(unit << 4)));
        }

    float mst[2][2] = {{-1e30f, -1e30f}, {-1e30f, -1e30f}};
    float lst[2][2] = {{0.f, 0.f}, {0.f, 0.f}};
    float oacc[2][8][4];
#pragma unroll
    for (int mt = 0; mt < 2; mt++)
#pragma unroll
        for (int et = 0; et < 8; et++)
#pragma unroll
            for (int j = 0; j < 4; j++) oacc[mt][et][j] = 0.f;

    int buf = 0;
    for (int it = 0; it < 32; ++it) {
        if (it + 1 < 32) cp_wait<1>(); else cp_wait<0>();
        __syncthreads();
        if (it + 2 < 32) {
            int nb = buf + 2; if (nb >= 3) nb -= 3;
            load_kv(it + 2, nb);
            cp_commit();
        }

        uint32_t kb = sb + 16384u + (uint32_t)buf * 16384u;
        uint32_t vb = kb + 8192u;

        float s_[2][8][4];
#pragma unroll
        for (int mt = 0; mt < 2; mt++)
#pragma unroll
            for (int nt = 0; nt < 8; nt++)
#pragma unroll
                for (int j = 0; j < 4; j++) s_[mt][nt][j] = 0.f;
#pragma unroll
        for (int j = 0; j < 4; j++) {
            uint32_t bf[8][2];
#pragma unroll
            for (int p = 0; p < 4; p++) {
                uint32_t r[4];
                int row = p * 16 + (lane & 7) + ((lane >> 4) & 1) * 8;
                int unit = 2 * j + ((lane >> 3) & 1);
                ldmx4(r, kb + sw128((uint32_t)(row << 7) + (uint32_t)(unit << 4)));
                bf[2 * p][0] = r[0]; bf[2 * p][1] = r[1];
                bf[2 * p + 1][0] = r[2]; bf[2 * p + 1][1] = r[3];
            }
#pragma unroll
            for (int mt = 0; mt < 2; mt++)
#pragma unroll
                for (int nt = 0; nt < 8; nt++)
                    mma16(s_[mt][nt], aQ[mt][j], bf[nt]);
        }

        uint32_t pp[2][8][2];
#pragma unroll
        for (int mt = 0; mt < 2; mt++) {
            float r0max = -1e30f, r1max = -1e30f;
#pragma unroll
            for (int nt = 0; nt < 8; nt++) {
                r0max = fmaxf(r0max, fmaxf(s_[mt][nt][0], s_[mt][nt][1]));
                r1max = fmaxf(r1max, fmaxf(s_[mt][nt][2], s_[mt][nt][3]));
            }
            r0max = fmaxf(r0max, __shfl_xor_sync(0xffffffffu, r0max, 1));
            r0max = fmaxf(r0max, __shfl_xor_sync(0xffffffffu, r0max, 2));
            r1max = fmaxf(r1max, __shfl_xor_sync(0xffffffffu, r1max, 1));
            r1max = fmaxf(r1max, __shfl_xor_sync(0xffffffffu, r1max, 2));

            float mn0 = fmaxf(mst[mt][0], r0max), mn1 = fmaxf(mst[mt][1], r1max);
            float al0 = exp2f((mst[mt][0] - mn0) * c2);
            float al1 = exp2f((mst[mt][1] - mn1) * c2);
            float mc0 = mn0 * c2, mc1 = mn1 * c2;
#pragma unroll
            for (int nt = 0; nt < 8; nt++) {
                pp[mt][nt][0] = h2exp2(packh2(fmaf(s_[mt][nt][0], c2, -mc0),
                                              fmaf(s_[mt][nt][1], c2, -mc0)));
                pp[mt][nt][1] = h2exp2(packh2(fmaf(s_[mt][nt][2], c2, -mc1),
                                              fmaf(s_[mt][nt][3], c2, -mc1)));
            }
            uint32_t t0 = hadd2(hadd2(hadd2(pp[mt][0][0], pp[mt][1][0]),
                                      hadd2(pp[mt][2][0], pp[mt][3][0])),
                                hadd2(hadd2(pp[mt][4][0], pp[mt][5][0]),
                                      hadd2(pp[mt][6][0], pp[mt][7][0])));
            uint32_t t1 = hadd2(hadd2(hadd2(pp[mt][0][1], pp[mt][1][1]),
                                      hadd2(pp[mt][2][1], pp[mt][3][1])),
                                hadd2(hadd2(pp[mt][4][1], pp[mt][5][1]),
                                      hadd2(pp[mt][6][1], pp[mt][7][1])));
            float2 f0 = h2tof2(t0);
            float2 f1 = h2tof2(t1);
            float sum0 = f0.x + f0.y;
            float sum1 = f1.x + f1.y;
            sum0 += __shfl_xor_sync(0xffffffffu, sum0, 1);
            sum0 += __shfl_xor_sync(0xffffffffu, sum0, 2);
            sum1 += __shfl_xor_sync(0xffffffffu, sum1, 1);
            sum1 += __shfl_xor_sync(0xffffffffu, sum1, 2);

            lst[mt][0] = lst[mt][0] * al0 + sum0;  mst[mt][0] = mn0;
            lst[mt][1] = lst[mt][1] * al1 + sum1;  mst[mt][1] = mn1;
#pragma unroll
            for (int et = 0; et < 8; et++) {
                oacc[mt][et][0] *= al0; oacc[mt][et][1] *= al0;
                oacc[mt][et][2] *= al1; oacc[mt][et][3] *= al1;
            }
        }

#pragma unroll
        for (int j2 = 0; j2 < 4; j2++) {
            uint32_t pa[2][4];
#pragma unroll
            for (int mt = 0; mt < 2; mt++) {
                pa[mt][0] = pp[mt][2 * j2][0];
                pa[mt][1] = pp[mt][2 * j2][1];
                pa[mt][2] = pp[mt][2 * j2 + 1][0];
                pa[mt][3] = pp[mt][2 * j2 + 1][1];
            }
#pragma unroll
            for (int p = 0; p < 4; p++) {
                uint32_t r[4];
                int row = j2 * 16 + (lane & 7) + ((lane >> 3) & 1) * 8;
                int unit = p * 2 + (lane >> 4);
                ldmx4t(r, vb + sw128((uint32_t)(row << 7) + (uint32_t)(unit << 4)));
                uint32_t bf0[2] = { r[0], r[1] };
                uint32_t bf1[2] = { r[2], r[3] };
#pragma unroll
                for (int mt = 0; mt < 2; mt++) {
                    mma16(oacc[mt][2 * p],     pa[mt], bf0);
                    mma16(oacc[mt][2 * p + 1], pa[mt], bf1);
                }
            }
        }
        if (++buf == 3) buf = 0;
    }

    __half* Og = O + base + (size_t)m0 * 512;
#pragma unroll
    for (int mt = 0; mt < 2; mt++) {
        const float i0 = 1.f / lst[mt][0];
        const float i1 = 1.f / lst[mt][1];
        int r0 = w * 32 + mt * 16 + qr;
#pragma unroll
        for (int et = 0; et < 8; et++) {
            int c = et * 8 + qc * 2;
            *(uint32_t*)(Og + (size_t)r0 * 512 + c)       = packh2(oacc[mt][et][0] * i0, oacc[mt][et][1] * i0);
            *(uint32_t*)(Og + (size_t)(r0 + 8) * 512 + c) = packh2(oacc[mt][et][2] * i1, oacc[mt][et][3] * i1);
        }
    }
}

// ---------------------------------------------------------------------------
// Launch
// ---------------------------------------------------------------------------
extern "C" void kernel_launch(void* const* d_in, const int* in_sizes, int n_in,
                              void* d_out, int out_size)
{
    const float* x1 = (const float*)d_in[0];
    const float* x2 = (const float*)d_in[1];
    const float* r  = (const float*)d_in[2];
    const float* W1 = (const float*)d_in[3];
    const float* b1 = (const float*)d_in[4];
    const float* W2 = (const float*)d_in[5];
    const float* b2 = (const float*)d_in[6];
    const float* Wq = (const float*)d_in[7];
    const float* Wk = (const float*)d_in[8];
    const float* Wv = (const float*)d_in[9];
    const float* Wo = (const float*)d_in[10];
    float* out = (float*)d_out;

    __half *H1, *H2, *QH, *KH, *VH, *Ob;
    __half *x1h, *x2h, *rh, *W1t, *W2h, *Wqh, *Wkh, *Wvh, *Wot, *Wqc, *Wkc;
    float *bq, *bk, *zb;
    cudaGetSymbolAddress((void**)&H1,  g_H1);
    cudaGetSymbolAddress((void**)&H2,  g_H2);
    cudaGetSymbolAddress((void**)&QH,  g_QH);
    cudaGetSymbolAddress((void**)&KH,  g_KH);
    cudaGetSymbolAddress((void**)&VH,  g_VH);
    cudaGetSymbolAddress((void**)&Ob,  g_O);
    cudaGetSymbolAddress((void**)&x1h, g_x1h);
    cudaGetSymbolAddress((void**)&x2h, g_x2h);
    cudaGetSymbolAddress((void**)&rh,  g_rh);
    cudaGetSymbolAddress((void**)&W1t, g_W1t);
    cudaGetSymbolAddress((void**)&W2h, g_W2h);
    cudaGetSymbolAddress((void**)&Wqh, g_Wqh);
    cudaGetSymbolAddress((void**)&Wkh, g_Wkh);
    cudaGetSymbolAddress((void**)&Wvh, g_Wvh);
    cudaGetSymbolAddress((void**)&Wot, g_Wot);
    cudaGetSymbolAddress((void**)&Wqc, g_Wqc);
    cudaGetSymbolAddress((void**)&Wkc, g_Wkc);
    cudaGetSymbolAddress((void**)&bq,  g_bq);
    cudaGetSymbolAddress((void**)&bk,  g_bk);
    cudaGetSymbolAddress((void**)&zb,  g_zb);

    cudaFuncSetAttribute(flash_h, cudaFuncAttributeMaxDynamicSharedMemorySize, FL_SMEM);
    cudaFuncSetAttribute((const void*)gemm_hb<true,  true,  false>, cudaFuncAttributeMaxDynamicSharedMemorySize, GEMM_SMEM);
    cudaFuncSetAttribute((const void*)gemm_hb<false, true,  false>, cudaFuncAttributeMaxDynamicSharedMemorySize, GEMM_SMEM);
    cudaFuncSetAttribute((const void*)gemm_hb<false, false, false>, cudaFuncAttributeMaxDynamicSharedMemorySize, GEMM_SMEM);
    cudaFuncSetAttribute((const void*)gemm_hb<false, false, true >, cudaFuncAttributeMaxDynamicSharedMemorySize, GEMM_SMEM);

    // --- pre-pass ---
    prep_inputs<<<dim3(1024, 1, 3), 256>>>((const float4*)x1, (const float4*)x2, (const float4*)r,
                                           (uint4*)x1h, (uint4*)x2h, (uint4*)rh);
    prep_weights<<<dim3(128, 1, 6), 256>>>(W1, W2, Wq, Wk, Wv, Wo,
                                           W1t, W2h, Wqh, Wkh, Wvh, Wot);
    bias_comp<<<2, 512>>>(Wq, Wk, b2, bq, bk);

    // --- weight composition: Wqc = Wq@W2^T, Wkc = Wk@W2^T  (512x512x512) ---
    gemm_hb<false, false, false><<<dim3(4, 4, 2), 256, GEMM_SMEM>>>(
        Wqh, Wkh, Wqh, W2h, W2h, W2h, nullptr, nullptr, nullptr,
        Wqc, Wkc, Wqc, 512, 512);

    // --- MLP layer 1 (x1 -> H1, x2 -> H2) ---
    gemm_hb<true, true, false><<<dim3(4, 128, 2), 256, GEMM_SMEM>>>(
        x1h, x2h, x1h, W1t, W1t, W1t, b1, b1, b1, H1, H2, H1, 128, 512);

    // --- fused projections: QH = H2@Wqc^T + bq, KH = H1@Wkc^T + bk, VH = r@Wv^T ---
    gemm_hb<false, true, false><<<dim3(4, 128, 3), 256, GEMM_SMEM>>>(
        H2, H1, rh, Wqc, Wkc, Wvh, bq, bk, zb, QH, KH, VH, 512, 512);

    // --- attention ---
    flash_h<<<dim3(16, 64), 128, FL_SMEM>>>(QH, KH, VH, Ob);

    // --- output projection (f32 out) ---
    gemm_hb<false, false, true><<<dim3(4, 128, 1), 256, GEMM_SMEM>>>(
        Ob, Ob, Ob, Wot, Wot, Wot, nullptr, nullptr, nullptr, out, out, out, 512, 512);
}

// round 11
// speedup vs baseline: 1.1030x; 1.1030x over previous
#include <cuda_runtime.h>
#include <cuda_fp16.h>
#include <cstdint>

// ---------------------------------------------------------------------------
// Scratch (device globals; allocation-free per harness rules)
// ---------------------------------------------------------------------------
#define MROWS 16384   // B*n = 8*2048

__device__ __half g_H1 [MROWS * 512];   // relu(x1@W1+b1)
__device__ __half g_H2 [MROWS * 512];   // relu(x2@W1+b1)
__device__ __half g_QH [MROWS * 512];
__device__ __half g_KH [MROWS * 512];
__device__ __half g_VH [MROWS * 512];
__device__ __half g_O  [MROWS * 512];
__device__ __half g_x1h[MROWS * 128];
__device__ __half g_x2h[MROWS * 128];
__device__ __half g_rh [MROWS * 512];
__device__ __half g_W1t[512 * 128];     // W1^T -> [N=512][K=128]
__device__ __half g_W2h[512 * 512];     // W2 direct [c][d] fp16
__device__ __half g_Wqh[512 * 512];     // Wq flat [j][d]
__device__ __half g_Wkh[512 * 512];
__device__ __half g_Wvh[512 * 512];
__device__ __half g_Wot[512 * 512];     // [n=d][k=h*64+e] gathered from Wo
__device__ __half g_Wqc[512 * 512];     // Wq@W2^T  [j][c]
__device__ __half g_Wkc[512 * 512];     // Wk@W2^T  [j][c]
__device__ float  g_bq [512];           // Wq@b2
__device__ float  g_bk [512];           // Wk@b2
__device__ float  g_zb [512];           // zeros (VH bias)

// ---------------------------------------------------------------------------
// Helpers
// ---------------------------------------------------------------------------
__device__ __forceinline__ uint32_t smem_u32(const void* p) {
    uint32_t a;
    asm("{ .reg .u64 t; cvta.to.shared.u64 t, %1; cvt.u32.u64 %0, t; }" : "=r"(a) : "l"(p));
    return a;
}
__device__ __forceinline__ uint32_t sw128(uint32_t o) { return o ^ ((o >> 3) & 0x70); }

__device__ __forceinline__ void cp_async16(uint32_t dst, const void* src) {
    asm volatile("cp.async.cg.shared.global [%0], [%1], 16;" :: "r"(dst), "l"(src) : "memory");
}
__device__ __forceinline__ void cp_commit() {
    asm volatile("cp.async.commit_group;" ::: "memory");
}
template<int N> __device__ __forceinline__ void cp_wait() {
    asm volatile("cp.async.wait_group %0;" :: "n"(N) : "memory");
}

__device__ __forceinline__ void ldmx4(uint32_t* r, uint32_t addr) {
    asm volatile("ldmatrix.sync.aligned.m8n8.x4.shared.b16 {%0,%1,%2,%3}, [%4];"
                 : "=r"(r[0]), "=r"(r[1]), "=r"(r[2]), "=r"(r[3]) : "r"(addr));
}
__device__ __forceinline__ void ldmx4t(uint32_t* r, uint32_t addr) {
    asm volatile("ldmatrix.sync.aligned.m8n8.x4.trans.shared.b16 {%0,%1,%2,%3}, [%4];"
                 : "=r"(r[0]), "=r"(r[1]), "=r"(r[2]), "=r"(r[3]) : "r"(addr));
}
__device__ __forceinline__ void mma16(float* c, const uint32_t* a, const uint32_t* b) {
    asm volatile(
        "mma.sync.aligned.m16n8k16.row.col.f32.f16.f16.f32 "
        "{%0,%1,%2,%3}, {%4,%5,%6,%7}, {%8,%9}, {%0,%1,%2,%3};"
        : "+f"(c[0]), "+f"(c[1]), "+f"(c[2]), "+f"(c[3])
        : "r"(a[0]), "r"(a[1]), "r"(a[2]), "r"(a[3]), "r"(b[0]), "r"(b[1]));
}
__device__ __forceinline__ uint32_t packh2(float a, float b) {
    __half2 h = __floats2half2_rn(a, b);
    return *(uint32_t*)&h;
}
__device__ __forceinline__ uint32_t h2exp2(uint32_t x) {
    uint32_t y;
    asm("ex2.approx.f16x2 %0, %1;" : "=r"(y) : "r"(x));
    return y;
}
__device__ __forceinline__ float2 h2tof2(uint32_t x) {
    __half2 h = *(__half2*)&x;
    return __half22float2(h);
}
__device__ __forceinline__ uint32_t hadd2(uint32_t a, uint32_t b) {
    uint32_t d;
    asm("add.f16x2 %0, %1, %2;" : "=r"(d) : "r"(a), "r"(b));
    return d;
}

// ---------------------------------------------------------------------------
// Pre-pass kernels
// ---------------------------------------------------------------------------
__global__ void prep_inputs(const float4* __restrict__ x1, const float4* __restrict__ x2,
                            const float4* __restrict__ r,
                            uint4* __restrict__ x1h, uint4* __restrict__ x2h,
                            uint4* __restrict__ rh)
{
    const int z = blockIdx.z;
    const float4* S = (z == 0) ? x1 : (z == 1) ? x2 : r;
    uint4* D = (z == 0) ? x1h : (z == 1) ? x2h : rh;
    const int n8 = (z == 2) ? (MROWS * 512 / 8) : (MROWS * 128 / 8);
    for (int i = blockIdx.x * 256 + threadIdx.x; i < n8; i += 262144) {
        float4 a = S[2 * i], b = S[2 * i + 1];
        uint4 u;
        u.x = packh2(a.x, a.y); u.y = packh2(a.z, a.w);
        u.z = packh2(b.x, b.y); u.w = packh2(b.z, b.w);
        D[i] = u;
    }
}
__global__ void prep_weights(const float* __restrict__ W1, const float* __restrict__ W2,
                             const float* __restrict__ Wq, const float* __restrict__ Wk,
                             const float* __restrict__ Wv, const float* __restrict__ Wo,
                             __half* __restrict__ W1t, __half* __restrict__ W2h,
                             __half* __restrict__ Wqh, __half* __restrict__ Wkh,
                             __half* __restrict__ Wvh, __half* __restrict__ Wot)
{
    const int z = blockIdx.z;
    const int t0 = blockIdx.x * 256 + threadIdx.x;
    if (z == 0) { for (int i = t0; i < 262144; i += 32768) Wqh[i] = __float2half(Wq[i]); }
    else if (z == 1) { for (int i = t0; i < 262144; i += 32768) Wkh[i] = __float2half(Wk[i]); }
    else if (z == 2) { for (int i = t0; i < 262144; i += 32768) Wvh[i] = __float2half(Wv[i]); }
    else if (z == 3) {
        for (int i = t0; i < 262144; i += 32768) {
            int n = i >> 9, k = i & 511, h = k >> 6, e = k & 63;
            Wot[i] = __float2half(Wo[((size_t)h * 512 + n) * 64 + e]);
        }
    } else if (z == 4) {
        for (int i = t0; i < 65536; i += 32768) {
            int n = i >> 7, k = i & 127;
            W1t[i] = __float2half(W1[(size_t)k * 512 + n]);
        }
    } else {
        for (int i = t0; i < 262144; i += 32768) W2h[i] = __float2half(W2[i]);
    }
}
// bq = Wq @ b2, bk = Wk @ b2  (f32-exact; grid 2, block 512)
__global__ void bias_comp(const float* __restrict__ Wq, const float* __restrict__ Wk,
                          const float* __restrict__ b2,
                          float* __restrict__ bq, float* __restrict__ bk)
{
    const float* W = (blockIdx.x == 0) ? Wq : Wk;
    float* o = (blockIdx.x == 0) ? bq : bk;
    int j = threadIdx.x;
    float s = 0.f;
    for (int d = 0; d < 512; d++) s += W[(size_t)j * 512 + d] * b2[d];
    o[j] = s;
}

// ---------------------------------------------------------------------------
// Batched fp16 GEMM: C[M,N] = act(A[M,K] @ B^T + bias_z), z selects (A,B,C,bias)
// CTA tile 128x128x64, 256 threads, warp tile 32x64, 3-stage cp.async.
// ---------------------------------------------------------------------------
#define GSTAGE 32768
#define GEMM_SMEM (3 * GSTAGE)

template<bool RELU, bool BIAS, bool OUTF32>
__global__ __launch_bounds__(256, 2)
void gemm_hb(const __half* __restrict__ A0, const __half* __restrict__ A1, const __half* __restrict__ A2,
             const __half* __restrict__ B0, const __half* __restrict__ B1, const __half* __restrict__ B2,
             const float* __restrict__ bias0, const float* __restrict__ bias1, const float* __restrict__ bias2,
             void* __restrict__ C0, void* __restrict__ C1, void* __restrict__ C2,
             int K, int ldc)
{
    const int z = blockIdx.z;
    const __half* A = (z == 0) ? A0 : (z == 1) ? A1 : A2;
    const __half* B = (z == 0) ? B0 : (z == 1) ? B1 : B2;
    const float* bias = (z == 0) ? bias0 : (z == 1) ? bias1 : bias2;
    void* Cout = (z == 0) ? C0 : (z == 1) ? C1 : C2;

    extern __shared__ char smem[];
    const uint32_t sb = smem_u32(smem);
    const int tid = threadIdx.x, w = tid >> 5, lane = tid & 31;
    const int qr = lane >> 2, qc = lane & 3;
    const int m0 = blockIdx.y * 128, n0 = blockIdx.x * 128;
    const int wm = (w & 3) * 32, wn = (w >> 2) * 64;
    const int T = K >> 6;

    auto load_tile = [&](int t, int s) {
        uint32_t ab = sb + (uint32_t)s * GSTAGE, bb = ab + 16384;
        int k0 = t << 6;
#pragma unroll
        for (int i = 0; i < 4; i++) {
            int u = tid + i * 256;
            int row = u >> 3, cu = u & 7;
            uint32_t sw = sw128((uint32_t)(row << 7) + (uint32_t)(cu << 4));
            cp_async16(ab + sw, A + (size_t)(m0 + row) * K + k0 + cu * 8);
            cp_async16(bb + sw, B + (size_t)(n0 + row) * K + k0 + cu * 8);
        }
    };

    float acc[2][8][4];
#pragma unroll
    for (int mt = 0; mt < 2; mt++)
#pragma unroll
        for (int nt = 0; nt < 8; nt++)
#pragma unroll
            for (int j = 0; j < 4; j++) acc[mt][nt][j] = 0.f;

    load_tile(0, 0);
    cp_commit();
    if (T > 1) { load_tile(1, 1); cp_commit(); }

    int buf = 0;
    for (int t = 0; t < T; t++) {
        if (t + 1 < T) cp_wait<1>(); else cp_wait<0>();
        __syncthreads();
        if (t + 2 < T) {
            int nb = buf + 2; if (nb >= 3) nb -= 3;
            load_tile(t + 2, nb);
            cp_commit();
        }
        uint32_t ab = sb + (uint32_t)buf * GSTAGE, bb = ab + 16384;
#pragma unroll
        for (int j = 0; j < 4; j++) {
            uint32_t af[2][4], bf[8][2];
#pragma unroll
            for (int mt = 0; mt < 2; mt++) {
                int row = wm + mt * 16 + (lane & 7) + ((lane >> 3) & 1) * 8;
                int unit = 2 * j + (lane >> 4);
                ldmx4(af[mt], ab + sw128((uint32_t)(row << 7) + (uint32_t)(unit << 4)));
            }
#pragma unroll
            for (int p = 0; p < 4; p++) {
                uint32_t r[4];
                int row = wn + p * 16 + (lane & 7) + ((lane >> 4) & 1) * 8;
                int unit = 2 * j + ((lane >> 3) & 1);
                ldmx4(r, bb + sw128((uint32_t)(row << 7) + (uint32_t)(unit << 4)));
                bf[2 * p][0] = r[0]; bf[2 * p][1] = r[1];
                bf[2 * p + 1][0] = r[2]; bf[2 * p + 1][1] = r[3];
            }
#pragma unroll
            for (int mt = 0; mt < 2; mt++)
#pragma unroll
                for (int nt = 0; nt < 8; nt++)
                    mma16(acc[mt][nt], af[mt], bf[nt]);
        }
        if (++buf == 3) buf = 0;
    }

#pragma unroll
    for (int mt = 0; mt < 2; mt++) {
#pragma unroll
        for (int nt = 0; nt < 8; nt++) {
            int row = m0 + wm + mt * 16 + qr;
            int col = n0 + wn + nt * 8 + qc * 2;
            float b0 = BIAS ? bias[col] : 0.f;
            float b1 = BIAS ? bias[col + 1] : 0.f;
            float v0 = acc[mt][nt][0] + b0, v1 = acc[mt][nt][1] + b1;
            float v2 = acc[mt][nt][2] + b0, v3 = acc[mt][nt][3] + b1;
            if (RELU) {
                v0 = fmaxf(v0, 0.f); v1 = fmaxf(v1, 0.f);
                v2 = fmaxf(v2, 0.f); v3 = fmaxf(v3, 0.f);
            }
            if (OUTF32) {
                float* C = (float*)Cout;
                *(float2*)(C + (size_t)row * ldc + col)       = make_float2(v0, v1);
                *(float2*)(C + (size_t)(row + 8) * ldc + col) = make_float2(v2, v3);
            } else {
                __half* C = (__half*)Cout;
                *(uint32_t*)(C + (size_t)row * ldc + col)       = packh2(v0, v1);
                *(uint32_t*)(C + (size_t)(row + 8) * ldc + col) = packh2(v2, v3);
            }
        }
    }
}

// ---------------------------------------------------------------------------
// Flash attention (R9 config, occupancy 2): grid (16,64), 128-thread CTA,
// 4 warps x 32 q-rows; f16x2 exp; P in registers; 3-stage KV pipeline;
// HADD2-tree row sums.  smem: Q 16KB + 3 x 16KB = 64KB.
// ---------------------------------------------------------------------------
#define FL_SMEM (16384 + 3 * 16384)

__global__ __launch_bounds__(128, 2)
void flash_h(const __half* __restrict__ QH, const __half* __restrict__ KH,
             const __half* __restrict__ VH, __half* __restrict__ O)
{
    extern __shared__ char smc[];
    const uint32_t sb = smem_u32(smc);
    const int tid  = threadIdx.x;
    const int w    = tid >> 5;
    const int lane = tid & 31;
    const int qr   = lane >> 2;
    const int qc   = lane & 3;
    const float c2 = 0.18033688011112042f;   // 0.125 * log2(e)

    const int m0 = blockIdx.x * 128;
    const int bh = blockIdx.y;
    const size_t base = (size_t)(bh >> 3) * 2048 * 512 + (size_t)(bh & 7) * 64;

    {
        const __half* Qg = QH + base + (size_t)m0 * 512;
#pragma unroll
        for (int i = 0; i < 8; i++) {
            int u = tid + i * 128;
            int row = u >> 3, cu = u & 7;
            cp_async16(sb + sw128((uint32_t)(row << 7) + (uint32_t)(cu << 4)),
                       Qg + (size_t)row * 512 + cu * 8);
        }
        cp_commit();
    }
    auto load_kv = [&](int it, int s) {
        uint32_t kb = sb + 16384u + (uint32_t)s * 16384u;
        uint32_t vb = kb + 8192u;
        const __half* Kg = KH + base + (size_t)(it * 64) * 512;
        const __half* Vg = VH + base + (size_t)(it * 64) * 512;
#pragma unroll
        for (int i = 0; i < 4; i++) {
            int u = tid + i * 128;
            int row = u >> 3, cu = u & 7;
            uint32_t sw = sw128((uint32_t)(row << 7) + (uint32_t)(cu << 4));
            cp_async16(kb + sw, Kg + (size_t)row * 512 + cu * 8);
            cp_async16(vb + sw, Vg + (size_t)row * 512 + cu * 8);
        }
    };
    load_kv(0, 0);
    cp_commit();
    load_kv(1, 1);
    cp_commit();

    cp_wait<2>();
    __syncthreads();

    uint32_t aQ[2][4][4];
#pragma unroll
    for (int mt = 0; mt < 2; mt++)
#pragma unroll
        for (int j = 0; j < 4; j++) {
            int row = w * 32 + mt * 16 + (lane & 7) + ((lane >> 3) & 1) * 8;
            int unit = 2 * j + (lane >> 4);
            ldmx4(aQ[mt][j], sb + sw128((uint32_t)(row << 7) + (uint32_t)(unit << 4)));
        }

    float mst[2][2] = {{-1e30f, -1e30f}, {-1e30f, -1e30f}};
    float lst[2][2] = {{0.f, 0.f}, {0.f, 0.f}};
    float oacc[2][8][4];
#pragma unroll
    for (int mt = 0; mt < 2; mt++)
#pragma unroll
        for (int et = 0; et < 8; et++)
#pragma unroll
            for (int j = 0; j < 4; j++) oacc[mt][et][j] = 0.f;

    int buf = 0;
    for (int it = 0; it < 32; ++it) {
        if (it + 1 < 32) cp_wait<1>(); else cp_wait<0>();
        __syncthreads();
        if (it + 2 < 32) {
            int nb = buf + 2; if (nb >= 3) nb -= 3;
            load_kv(it + 2, nb);
            cp_commit();
        }

        uint32_t kb = sb + 16384u + (uint32_t)buf * 16384u;
        uint32_t vb = kb + 8192u;

        float s_[2][8][4];
#pragma unroll
        for (int mt = 0; mt < 2; mt++)
#pragma unroll
            for (int nt = 0; nt < 8; nt++)
#pragma unroll
                for (int j = 0; j < 4; j++) s_[mt][nt][j] = 0.f;
#pragma unroll
        for (int j = 0; j < 4; j++) {
            uint32_t bf[8][2];
#pragma unroll
            for (int p = 0; p < 4; p++) {
                uint32_t r[4];
                int row = p * 16 + (lane & 7) + ((lane >> 4) & 1) * 8;
                int unit = 2 * j + ((lane >> 3) & 1);
                ldmx4(r, kb + sw128((uint32_t)(row << 7) + (uint32_t)(unit << 4)));
                bf[2 * p][0] = r[0]; bf[2 * p][1] = r[1];
                bf[2 * p + 1][0] = r[2]; bf[2 * p + 1][1] = r[3];
            }
#pragma unroll
            for (int mt = 0; mt < 2; mt++)
#pragma unroll
                for (int nt = 0; nt < 8; nt++)
                    mma16(s_[mt][nt], aQ[mt][j], bf[nt]);
        }

        uint32_t pp[2][8][2];
#pragma unroll
        for (int mt = 0; mt < 2; mt++) {
            float r0max = -1e30f, r1max = -1e30f;
#pragma unroll
            for (int nt = 0; nt < 8; nt++) {
                r0max = fmaxf(r0max, fmaxf(s_[mt][nt][0], s_[mt][nt][1]));
                r1max = fmaxf(r1max, fmaxf(s_[mt][nt][2], s_[mt][nt][3]));
            }
            r0max = fmaxf(r0max, __shfl_xor_sync(0xffffffffu, r0max, 1));
            r0max = fmaxf(r0max, __shfl_xor_sync(0xffffffffu, r0max, 2));
            r1max = fmaxf(r1max, __shfl_xor_sync(0xffffffffu, r1max, 1));
            r1max = fmaxf(r1max, __shfl_xor_sync(0xffffffffu, r1max, 2));

            float mn0 = fmaxf(mst[mt][0], r0max), mn1 = fmaxf(mst[mt][1], r1max);
            float al0 = exp2f((mst[mt][0] - mn0) * c2);
            float al1 = exp2f((mst[mt][1] - mn1) * c2);
            float mc0 = mn0 * c2, mc1 = mn1 * c2;
#pragma unroll
            for (int nt = 0; nt < 8; nt++) {
                pp[mt][nt][0] = h2exp2(packh2(fmaf(s_[mt][nt][0], c2, -mc0),
                                              fmaf(s_[mt][nt][1], c2, -mc0)));
                pp[mt][nt][1] = h2exp2(packh2(fmaf(s_[mt][nt][2], c2, -mc1),
                                              fmaf(s_[mt][nt][3], c2, -mc1)));
            }
            uint32_t t0 = hadd2(hadd2(hadd2(pp[mt][0][0], pp[mt][1][0]),
                                      hadd2(pp[mt][2][0], pp[mt][3][0])),
                                hadd2(hadd2(pp[mt][4][0], pp[mt][5][0]),
                                      hadd2(pp[mt][6][0], pp[mt][7][0])));
            uint32_t t1 = hadd2(hadd2(hadd2(pp[mt][0][1], pp[mt][1][1]),
                                      hadd2(pp[mt][2][1], pp[mt][3][1])),
                                hadd2(hadd2(pp[mt][4][1], pp[mt][5][1]),
                                      hadd2(pp[mt][6][1], pp[mt][7][1])));
            float2 f0 = h2tof2(t0);
            float2 f1 = h2tof2(t1);
            float sum0 = f0.x + f0.y;
            float sum1 = f1.x + f1.y;
            sum0 += __shfl_xor_sync(0xffffffffu, sum0, 1);
            sum0 += __shfl_xor_sync(0xffffffffu, sum0, 2);
            sum1 += __shfl_xor_sync(0xffffffffu, sum1, 1);
            sum1 += __shfl_xor_sync(0xffffffffu, sum1, 2);

            lst[mt][0] = lst[mt][0] * al0 + sum0;  mst[mt][0] = mn0;
            lst[mt][1] = lst[mt][1] * al1 + sum1;  mst[mt][1] = mn1;
#pragma unroll
            for (int et = 0; et < 8; et++) {
                oacc[mt][et][0] *= al0; oacc[mt][et][1] *= al0;
                oacc[mt][et][2] *= al1; oacc[mt][et][3] *= al1;
            }
        }

#pragma unroll
        for (int j2 = 0; j2 < 4; j2++) {
            uint32_t pa[2][4];
#pragma unroll
            for (int mt = 0; mt < 2; mt++) {
                pa[mt][0] = pp[mt][2 * j2][0];
                pa[mt][1] = pp[mt][2 * j2][1];
                pa[mt][2] = pp[mt][2 * j2 + 1][0];
                pa[mt][3] = pp[mt][2 * j2 + 1][1];
            }
#pragma unroll
            for (int p = 0; p < 4; p++) {
                uint32_t r[4];
                int row = j2 * 16 + (lane & 7) + ((lane >> 3) & 1) * 8;
                int unit = p * 2 + (lane >> 4);
                ldmx4t(r, vb + sw128((uint32_t)(row << 7) + (uint32_t)(unit << 4)));
                uint32_t bf0[2] = { r[0], r[1] };
                uint32_t bf1[2] = { r[2], r[3] };
#pragma unroll
                for (int mt = 0; mt < 2; mt++) {
                    mma16(oacc[mt][2 * p],     pa[mt], bf0);
                    mma16(oacc[mt][2 * p + 1], pa[mt], bf1);
                }
            }
        }
        if (++buf == 3) buf = 0;
    }

    __half* Og = O + base + (size_t)m0 * 512;
#pragma unroll
    for (int mt = 0; mt < 2; mt++) {
        const float i0 = 1.f / lst[mt][0];
        const float i1 = 1.f / lst[mt][1];
        int r0 = w * 32 + mt * 16 + qr;
#pragma unroll
        for (int et = 0; et < 8; et++) {
            int c = et * 8 + qc * 2;
            *(uint32_t*)(Og + (size_t)r0 * 512 + c)       = packh2(oacc[mt][et][0] * i0, oacc[mt][et][1] * i0);
            *(uint32_t*)(Og + (size_t)(r0 + 8) * 512 + c) = packh2(oacc[mt][et][2] * i1, oacc[mt][et][3] * i1);
        }
    }
}

// ---------------------------------------------------------------------------
// Launch
// ---------------------------------------------------------------------------
extern "C" void kernel_launch(void* const* d_in, const int* in_sizes, int n_in,
                              void* d_out, int out_size)
{
    const float* x1 = (const float*)d_in[0];
    const float* x2 = (const float*)d_in[1];
    const float* r  = (const float*)d_in[2];
    const float* W1 = (const float*)d_in[3];
    const float* b1 = (const float*)d_in[4];
    const float* W2 = (const float*)d_in[5];
    const float* b2 = (const float*)d_in[6];
    const float* Wq = (const float*)d_in[7];
    const float* Wk = (const float*)d_in[8];
    const float* Wv = (const float*)d_in[9];
    const float* Wo = (const float*)d_in[10];
    float* out = (float*)d_out;

    __half *H1, *H2, *QH, *KH, *VH, *Ob;
    __half *x1h, *x2h, *rh, *W1t, *W2h, *Wqh, *Wkh, *Wvh, *Wot, *Wqc, *Wkc;
    float *bq, *bk, *zb;
    cudaGetSymbolAddress((void**)&H1,  g_H1);
    cudaGetSymbolAddress((void**)&H2,  g_H2);
    cudaGetSymbolAddress((void**)&QH,  g_QH);
    cudaGetSymbolAddress((void**)&KH,  g_KH);
    cudaGetSymbolAddress((void**)&VH,  g_VH);
    cudaGetSymbolAddress((void**)&Ob,  g_O);
    cudaGetSymbolAddress((void**)&x1h, g_x1h);
    cudaGetSymbolAddress((void**)&x2h, g_x2h);
    cudaGetSymbolAddress((void**)&rh,  g_rh);
    cudaGetSymbolAddress((void**)&W1t, g_W1t);
    cudaGetSymbolAddress((void**)&W2h, g_W2h);
    cudaGetSymbolAddress((void**)&Wqh, g_Wqh);
    cudaGetSymbolAddress((void**)&Wkh, g_Wkh);
    cudaGetSymbolAddress((void**)&Wvh, g_Wvh);
    cudaGetSymbolAddress((void**)&Wot, g_Wot);
    cudaGetSymbolAddress((void**)&Wqc, g_Wqc);
    cudaGetSymbolAddress((void**)&Wkc, g_Wkc);
    cudaGetSymbolAddress((void**)&bq,  g_bq);
    cudaGetSymbolAddress((void**)&bk,  g_bk);
    cudaGetSymbolAddress((void**)&zb,  g_zb);

    cudaFuncSetAttribute(flash_h, cudaFuncAttributeMaxDynamicSharedMemorySize, FL_SMEM);
    cudaFuncSetAttribute((const void*)gemm_hb<true,  true,  false>, cudaFuncAttributeMaxDynamicSharedMemorySize, GEMM_SMEM);
    cudaFuncSetAttribute((const void*)gemm_hb<false, true,  false>, cudaFuncAttributeMaxDynamicSharedMemorySize, GEMM_SMEM);
    cudaFuncSetAttribute((const void*)gemm_hb<false, false, false>, cudaFuncAttributeMaxDynamicSharedMemorySize, GEMM_SMEM);
    cudaFuncSetAttribute((const void*)gemm_hb<false, false, true >, cudaFuncAttributeMaxDynamicSharedMemorySize, GEMM_SMEM);

    // --- pre-pass ---
    prep_inputs<<<dim3(1024, 1, 3), 256>>>((const float4*)x1, (const float4*)x2, (const float4*)r,
                                           (uint4*)x1h, (uint4*)x2h, (uint4*)rh);
    prep_weights<<<dim3(128, 1, 6), 256>>>(W1, W2, Wq, Wk, Wv, Wo,
                                           W1t, W2h, Wqh, Wkh, Wvh, Wot);
    bias_comp<<<2, 512>>>(Wq, Wk, b2, bq, bk);

    // --- weight composition: Wqc = Wq@W2^T, Wkc = Wk@W2^T  (512x512x512) ---
    gemm_hb<false, false, false><<<dim3(4, 4, 2), 256, GEMM_SMEM>>>(
        Wqh, Wkh, Wqh, W2h, W2h, W2h, nullptr, nullptr, nullptr,
        Wqc, Wkc, Wqc, 512, 512);

    // --- MLP layer 1 (x1 -> H1, x2 -> H2) ---
    gemm_hb<true, true, false><<<dim3(4, 128, 2), 256, GEMM_SMEM>>>(
        x1h, x2h, x1h, W1t, W1t, W1t, b1, b1, b1, H1, H2, H1, 128, 512);

    // --- fused projections: QH = H2@Wqc^T + bq, KH = H1@Wkc^T + bk, VH = r@Wv^T ---
    gemm_hb<false, true, false><<<dim3(4, 128, 3), 256, GEMM_SMEM>>>(
        H2, H1, rh, Wqc, Wkc, Wvh, bq, bk, zb, QH, KH, VH, 512, 512);

    // --- attention ---
    flash_h<<<dim3(16, 64), 128, FL_SMEM>>>(QH, KH, VH, Ob);

    // --- output projection (f32 out) ---
    gemm_hb<false, false, true><<<dim3(4, 128, 1), 256, GEMM_SMEM>>>(
        Ob, Ob, Ob, Wot, Wot, Wot, nullptr, nullptr, nullptr, out, out, out, 512, 512);
}

// round 12
// speedup vs baseline: 1.5334x; 1.3902x over previous
#include <cuda_runtime.h>
#include <cuda_fp16.h>
#include <cstdint>

// ---------------------------------------------------------------------------
// Scratch (device globals; allocation-free per harness rules)
// ---------------------------------------------------------------------------
#define MROWS 16384   // B*n = 8*2048

__device__ __half g_H1 [MROWS * 512];   // relu(x1@W1+b1)
__device__ __half g_H2 [MROWS * 512];   // relu(x2@W1+b1)
__device__ __half g_QH [MROWS * 512];
__device__ __half g_KH [MROWS * 512];
__device__ __half g_VH [MROWS * 512];
__device__ __half g_O  [MROWS * 512];
__device__ __half g_x1h[MROWS * 128];
__device__ __half g_x2h[MROWS * 128];
__device__ __half g_rh [MROWS * 512];
__device__ __half g_W1t[512 * 128];     // W1^T -> [N=512][K=128]
__device__ __half g_W2h[512 * 512];     // W2 direct [c][d] fp16
__device__ __half g_Wqh[512 * 512];     // Wq flat [j][d]
__device__ __half g_Wkh[512 * 512];
__device__ __half g_Wvh[512 * 512];
__device__ __half g_Wot[512 * 512];     // [n=d][k=h*64+e] gathered from Wo
__device__ __half g_Wqc[512 * 512];     // Wq@W2^T  [j][c]
__device__ __half g_Wkc[512 * 512];     // Wk@W2^T  [j][c]
__device__ float  g_bq [512];           // Wq@b2
__device__ float  g_bk [512];           // Wk@b2
__device__ float  g_zb [512];           // zeros (VH bias)

// ---------------------------------------------------------------------------
// Helpers
// ---------------------------------------------------------------------------
__device__ __forceinline__ uint32_t smem_u32(const void* p) {
    uint32_t a;
    asm("{ .reg .u64 t; cvta.to.shared.u64 t, %1; cvt.u32.u64 %0, t; }" : "=r"(a) : "l"(p));
    return a;
}
__device__ __forceinline__ uint32_t sw128(uint32_t o) { return o ^ ((o >> 3) & 0x70); }

__device__ __forceinline__ void cp_async16(uint32_t dst, const void* src) {
    asm volatile("cp.async.cg.shared.global [%0], [%1], 16;" :: "r"(dst), "l"(src) : "memory");
}
__device__ __forceinline__ void cp_commit() {
    asm volatile("cp.async.commit_group;" ::: "memory");
}
template<int N> __device__ __forceinline__ void cp_wait() {
    asm volatile("cp.async.wait_group %0;" :: "n"(N) : "memory");
}

__device__ __forceinline__ void ldmx4(uint32_t* r, uint32_t addr) {
    asm volatile("ldmatrix.sync.aligned.m8n8.x4.shared.b16 {%0,%1,%2,%3}, [%4];"
                 : "=r"(r[0]), "=r"(r[1]), "=r"(r[2]), "=r"(r[3]) : "r"(addr));
}
__device__ __forceinline__ void ldmx4t(uint32_t* r, uint32_t addr) {
    asm volatile("ldmatrix.sync.aligned.m8n8.x4.trans.shared.b16 {%0,%1,%2,%3}, [%4];"
                 : "=r"(r[0]), "=r"(r[1]), "=r"(r[2]), "=r"(r[3]) : "r"(addr));
}
__device__ __forceinline__ void mma16(float* c, const uint32_t* a, const uint32_t* b) {
    asm volatile(
        "mma.sync.aligned.m16n8k16.row.col.f32.f16.f16.f32 "
        "{%0,%1,%2,%3}, {%4,%5,%6,%7}, {%8,%9}, {%0,%1,%2,%3};"
        : "+f"(c[0]), "+f"(c[1]), "+f"(c[2]), "+f"(c[3])
        : "r"(a[0]), "r"(a[1]), "r"(a[2]), "r"(a[3]), "r"(b[0]), "r"(b[1]));
}
__device__ __forceinline__ uint32_t packh2(float a, float b) {
    __half2 h = __floats2half2_rn(a, b);
    return *(uint32_t*)&h;
}
__device__ __forceinline__ uint32_t h2exp2(uint32_t x) {
    uint32_t y;
    asm("ex2.approx.f16x2 %0, %1;" : "=r"(y) : "r"(x));
    return y;
}
__device__ __forceinline__ float2 h2tof2(uint32_t x) {
    __half2 h = *(__half2*)&x;
    return __half22float2(h);
}
__device__ __forceinline__ uint32_t hadd2(uint32_t a, uint32_t b) {
    uint32_t d;
    asm("add.f16x2 %0, %1, %2;" : "=r"(d) : "r"(a), "r"(b));
    return d;
}

// ---------------------------------------------------------------------------
// Pre-pass kernels
// ---------------------------------------------------------------------------
__global__ void prep_inputs(const float4* __restrict__ x1, const float4* __restrict__ x2,
                            const float4* __restrict__ r,
                            uint4* __restrict__ x1h, uint4* __restrict__ x2h,
                            uint4* __restrict__ rh)
{
    const int z = blockIdx.z;
    const float4* S = (z == 0) ? x1 : (z == 1) ? x2 : r;
    uint4* D = (z == 0) ? x1h : (z == 1) ? x2h : rh;
    const int n8 = (z == 2) ? (MROWS * 512 / 8) : (MROWS * 128 / 8);
    for (int i = blockIdx.x * 256 + threadIdx.x; i < n8; i += 262144) {
        float4 a = S[2 * i], b = S[2 * i + 1];
        uint4 u;
        u.x = packh2(a.x, a.y); u.y = packh2(a.z, a.w);
        u.z = packh2(b.x, b.y); u.w = packh2(b.z, b.w);
        D[i] = u;
    }
}
__global__ void prep_weights(const float* __restrict__ W1, const float* __restrict__ W2,
                             const float* __restrict__ Wq, const float* __restrict__ Wk,
                             const float* __restrict__ Wv, const float* __restrict__ Wo,
                             __half* __restrict__ W1t, __half* __restrict__ W2h,
                             __half* __restrict__ Wqh, __half* __restrict__ Wkh,
                             __half* __restrict__ Wvh, __half* __restrict__ Wot)
{
    const int z = blockIdx.z;
    const int t0 = blockIdx.x * 256 + threadIdx.x;
    if (z == 0) { for (int i = t0; i < 262144; i += 32768) Wqh[i] = __float2half(Wq[i]); }
    else if (z == 1) { for (int i = t0; i < 262144; i += 32768) Wkh[i] = __float2half(Wk[i]); }
    else if (z == 2) { for (int i = t0; i < 262144; i += 32768) Wvh[i] = __float2half(Wv[i]); }
    else if (z == 3) {
        for (int i = t0; i < 262144; i += 32768) {
            int n = i >> 9, k = i & 511, h = k >> 6, e = k & 63;
            Wot[i] = __float2half(Wo[((size_t)h * 512 + n) * 64 + e]);
        }
    } else if (z == 4) {
        for (int i = t0; i < 65536; i += 32768) {
            int n = i >> 7, k = i & 127;
            W1t[i] = __float2half(W1[(size_t)k * 512 + n]);
        }
    } else {
        for (int i = t0; i < 262144; i += 32768) W2h[i] = __float2half(W2[i]);
    }
}
// bq[j] = sum_d Wq[j][d]*b2[d], bk likewise.
// grid 1024 (512 q + 512 k), 128 threads; coalesced loads + block reduction.
__global__ void bias_comp(const float* __restrict__ Wq, const float* __restrict__ Wk,
                          const float* __restrict__ b2,
                          float* __restrict__ bq, float* __restrict__ bk)
{
    __shared__ float ws[4];
    const int b = blockIdx.x;
    const int j = b & 511;
    const float* W = (b < 512) ? Wq : Wk;
    float* o = (b < 512) ? bq : bk;
    const int t = threadIdx.x;

    float s = 0.f;
#pragma unroll
    for (int i = 0; i < 4; i++) {
        int d = t + i * 128;
        s += W[(size_t)j * 512 + d] * b2[d];
    }
#pragma unroll
    for (int off = 16; off > 0; off >>= 1)
        s += __shfl_xor_sync(0xffffffffu, s, off);
    if ((t & 31) == 0) ws[t >> 5] = s;
    __syncthreads();
    if (t == 0) o[j] = ws[0] + ws[1] + ws[2] + ws[3];
}

// ---------------------------------------------------------------------------
// Batched fp16 GEMM: C[M,N] = act(A[M,K] @ B^T + bias_z), z selects (A,B,C,bias)
// CTA tile 128x128x64, 256 threads, warp tile 32x64, 3-stage cp.async.
// ---------------------------------------------------------------------------
#define GSTAGE 32768
#define GEMM_SMEM (3 * GSTAGE)

template<bool RELU, bool BIAS, bool OUTF32>
__global__ __launch_bounds__(256, 2)
void gemm_hb(const __half* __restrict__ A0, const __half* __restrict__ A1, const __half* __restrict__ A2,
             const __half* __restrict__ B0, const __half* __restrict__ B1, const __half* __restrict__ B2,
             const float* __restrict__ bias0, const float* __restrict__ bias1, const float* __restrict__ bias2,
             void* __restrict__ C0, void* __restrict__ C1, void* __restrict__ C2,
             int K, int ldc)
{
    const int z = blockIdx.z;
    const __half* A = (z == 0) ? A0 : (z == 1) ? A1 : A2;
    const __half* B = (z == 0) ? B0 : (z == 1) ? B1 : B2;
    const float* bias = (z == 0) ? bias0 : (z == 1) ? bias1 : bias2;
    void* Cout = (z == 0) ? C0 : (z == 1) ? C1 : C2;

    extern __shared__ char smem[];
    const uint32_t sb = smem_u32(smem);
    const int tid = threadIdx.x, w = tid >> 5, lane = tid & 31;
    const int qr = lane >> 2, qc = lane & 3;
    const int m0 = blockIdx.y * 128, n0 = blockIdx.x * 128;
    const int wm = (w & 3) * 32, wn = (w >> 2) * 64;
    const int T = K >> 6;

    auto load_tile = [&](int t, int s) {
        uint32_t ab = sb + (uint32_t)s * GSTAGE, bb = ab + 16384;
        int k0 = t << 6;
#pragma unroll
        for (int i = 0; i < 4; i++) {
            int u = tid + i * 256;
            int row = u >> 3, cu = u & 7;
            uint32_t sw = sw128((uint32_t)(row << 7) + (uint32_t)(cu << 4));
            cp_async16(ab + sw, A + (size_t)(m0 + row) * K + k0 + cu * 8);
            cp_async16(bb + sw, B + (size_t)(n0 + row) * K + k0 + cu * 8);
        }
    };

    float acc[2][8][4];
#pragma unroll
    for (int mt = 0; mt < 2; mt++)
#pragma unroll
        for (int nt = 0; nt < 8; nt++)
#pragma unroll
            for (int j = 0; j < 4; j++) acc[mt][nt][j] = 0.f;

    load_tile(0, 0);
    cp_commit();
    if (T > 1) { load_tile(1, 1); cp_commit(); }

    int buf = 0;
    for (int t = 0; t < T; t++) {
        if (t + 1 < T) cp_wait<1>(); else cp_wait<0>();
        __syncthreads();
        if (t + 2 < T) {
            int nb = buf + 2; if (nb >= 3) nb -= 3;
            load_tile(t + 2, nb);
            cp_commit();
        }
        uint32_t ab = sb + (uint32_t)buf * GSTAGE, bb = ab + 16384;
#pragma unroll
        for (int j = 0; j < 4; j++) {
            uint32_t af[2][4], bf[8][2];
#pragma unroll
            for (int mt = 0; mt < 2; mt++) {
                int row = wm + mt * 16 + (lane & 7) + ((lane >> 3) & 1) * 8;
                int unit = 2 * j + (lane >> 4);
                ldmx4(af[mt], ab + sw128((uint32_t)(row << 7) + (uint32_t)(unit << 4)));
            }
#pragma unroll
            for (int p = 0; p < 4; p++) {
                uint32_t r[4];
                int row = wn + p * 16 + (lane & 7) + ((lane >> 4) & 1) * 8;
                int unit = 2 * j + ((lane >> 3) & 1);
                ldmx4(r, bb + sw128((uint32_t)(row << 7) + (uint32_t)(unit << 4)));
                bf[2 * p][0] = r[0]; bf[2 * p][1] = r[1];
                bf[2 * p + 1][0] = r[2]; bf[2 * p + 1][1] = r[3];
            }
#pragma unroll
            for (int mt = 0; mt < 2; mt++)
#pragma unroll
                for (int nt = 0; nt < 8; nt++)
                    mma16(acc[mt][nt], af[mt], bf[nt]);
        }
        if (++buf == 3) buf = 0;
    }

#pragma unroll
    for (int mt = 0; mt < 2; mt++) {
#pragma unroll
        for (int nt = 0; nt < 8; nt++) {
            int row = m0 + wm + mt * 16 + qr;
            int col = n0 + wn + nt * 8 + qc * 2;
            float b0 = BIAS ? bias[col] : 0.f;
            float b1 = BIAS ? bias[col + 1] : 0.f;
            float v0 = acc[mt][nt][0] + b0, v1 = acc[mt][nt][1] + b1;
            float v2 = acc[mt][nt][2] + b0, v3 = acc[mt][nt][3] + b1;
            if (RELU) {
                v0 = fmaxf(v0, 0.f); v1 = fmaxf(v1, 0.f);
                v2 = fmaxf(v2, 0.f); v3 = fmaxf(v3, 0.f);
            }
            if (OUTF32) {
                float* C = (float*)Cout;
                *(float2*)(C + (size_t)row * ldc + col)       = make_float2(v0, v1);
                *(float2*)(C + (size_t)(row + 8) * ldc + col) = make_float2(v2, v3);
            } else {
                __half* C = (__half*)Cout;
                *(uint32_t*)(C + (size_t)row * ldc + col)       = packh2(v0, v1);
                *(uint32_t*)(C + (size_t)(row + 8) * ldc + col) = packh2(v2, v3);
            }
        }
    }
}

// ---------------------------------------------------------------------------
// Flash attention (R9 config, occupancy 2): grid (16,64), 128-thread CTA,
// 4 warps x 32 q-rows; f16x2 exp; P in registers; 3-stage KV pipeline;
// HADD2-tree row sums.  smem: Q 16KB + 3 x 16KB = 64KB.
// ---------------------------------------------------------------------------
#define FL_SMEM (16384 + 3 * 16384)

__global__ __launch_bounds__(128, 2)
void flash_h(const __half* __restrict__ QH, const __half* __restrict__ KH,
             const __half* __restrict__ VH, __half* __restrict__ O)
{
    extern __shared__ char smc[];
    const uint32_t sb = smem_u32(smc);
    const int tid  = threadIdx.x;
    const int w    = tid >> 5;
    const int lane = tid & 31;
    const int qr   = lane >> 2;
    const int qc   = lane & 3;
    const float c2 = 0.18033688011112042f;   // 0.125 * log2(e)

    const int m0 = blockIdx.x * 128;
    const int bh = blockIdx.y;
    const size_t base = (size_t)(bh >> 3) * 2048 * 512 + (size_t)(bh & 7) * 64;

    {
        const __half* Qg = QH + base + (size_t)m0 * 512;
#pragma unroll
        for (int i = 0; i < 8; i++) {
            int u = tid + i * 128;
            int row = u >> 3, cu = u & 7;
            cp_async16(sb + sw128((uint32_t)(row << 7) + (uint32_t)(cu << 4)),
                       Qg + (size_t)row * 512 + cu * 8);
        }
        cp_commit();
    }
    auto load_kv = [&](int it, int s) {
        uint32_t kb = sb + 16384u + (uint32_t)s * 16384u;
        uint32_t vb = kb + 8192u;
        const __half* Kg = KH + base + (size_t)(it * 64) * 512;
        const __half* Vg = VH + base + (size_t)(it * 64) * 512;
#pragma unroll
        for (int i = 0; i < 4; i++) {
            int u = tid + i * 128;
            int row = u >> 3, cu = u & 7;
            uint32_t sw = sw128((uint32_t)(row << 7) + (uint32_t)(cu << 4));
            cp_async16(kb + sw, Kg + (size_t)row * 512 + cu * 8);
            cp_async16(vb + sw, Vg + (size_t)row * 512 + cu * 8);
        }
    };
    load_kv(0, 0);
    cp_commit();
    load_kv(1, 1);
    cp_commit();

    cp_wait<2>();
    __syncthreads();

    uint32_t aQ[2][4][4];
#pragma unroll
    for (int mt = 0; mt < 2; mt++)
#pragma unroll
        for (int j = 0; j < 4; j++) {
            int row = w * 32 + mt * 16 + (lane & 7) + ((lane >> 3) & 1) * 8;
            int unit = 2 * j + (lane >> 4);
            ldmx4(aQ[mt][j], sb + sw128((uint32_t)(row << 7) + (uint32_t)(unit << 4)));
        }

    float mst[2][2] = {{-1e30f, -1e30f}, {-1e30f, -1e30f}};
    float lst[2][2] = {{0.f, 0.f}, {0.f, 0.f}};
    float oacc[2][8][4];
#pragma unroll
    for (int mt = 0; mt < 2; mt++)
#pragma unroll
        for (int et = 0; et < 8; et++)
#pragma unroll
            for (int j = 0; j < 4; j++) oacc[mt][et][j] = 0.f;

    int buf = 0;
    for (int it = 0; it < 32; ++it) {
        if (it + 1 < 32) cp_wait<1>(); else cp_wait<0>();
        __syncthreads();
        if (it + 2 < 32) {
            int nb = buf + 2; if (nb >= 3) nb -= 3;
            load_kv(it + 2, nb);
            cp_commit();
        }

        uint32_t kb = sb + 16384u + (uint32_t)buf * 16384u;
        uint32_t vb = kb + 8192u;

        float s_[2][8][4];
#pragma unroll
        for (int mt = 0; mt < 2; mt++)
#pragma unroll
            for (int nt = 0; nt < 8; nt++)
#pragma unroll
                for (int j = 0; j < 4; j++) s_[mt][nt][j] = 0.f;
#pragma unroll
        for (int j = 0; j < 4; j++) {
            uint32_t bf[8][2];
#pragma unroll
            for (int p = 0; p < 4; p++) {
                uint32_t r[4];
                int row = p * 16 + (lane & 7) + ((lane >> 4) & 1) * 8;
                int unit = 2 * j + ((lane >> 3) & 1);
                ldmx4(r, kb + sw128((uint32_t)(row << 7) + (uint32_t)(unit << 4)));
                bf[2 * p][0] = r[0]; bf[2 * p][1] = r[1];
                bf[2 * p + 1][0] = r[2]; bf[2 * p + 1][1] = r[3];
            }
#pragma unroll
            for (int mt = 0; mt < 2; mt++)
#pragma unroll
                for (int nt = 0; nt < 8; nt++)
                    mma16(s_[mt][nt], aQ[mt][j], bf[nt]);
        }

        uint32_t pp[2][8][2];
#pragma unroll
        for (int mt = 0; mt < 2; mt++) {
            float r0max = -1e30f, r1max = -1e30f;
#pragma unroll
            for (int nt = 0; nt < 8; nt++) {
                r0max = fmaxf(r0max, fmaxf(s_[mt][nt][0], s_[mt][nt][1]));
                r1max = fmaxf(r1max, fmaxf(s_[mt][nt][2], s_[mt][nt][3]));
            }
            r0max = fmaxf(r0max, __shfl_xor_sync(0xffffffffu, r0max, 1));
            r0max = fmaxf(r0max, __shfl_xor_sync(0xffffffffu, r0max, 2));
            r1max = fmaxf(r1max, __shfl_xor_sync(0xffffffffu, r1max, 1));
            r1max = fmaxf(r1max, __shfl_xor_sync(0xffffffffu, r1max, 2));

            float mn0 = fmaxf(mst[mt][0], r0max), mn1 = fmaxf(mst[mt][1], r1max);
            float al0 = exp2f((mst[mt][0] - mn0) * c2);
            float al1 = exp2f((mst[mt][1] - mn1) * c2);
            float mc0 = mn0 * c2, mc1 = mn1 * c2;
#pragma unroll
            for (int nt = 0; nt < 8; nt++) {
                pp[mt][nt][0] = h2exp2(packh2(fmaf(s_[mt][nt][0], c2, -mc0),
                                              fmaf(s_[mt][nt][1], c2, -mc0)));
                pp[mt][nt][1] = h2exp2(packh2(fmaf(s_[mt][nt][2], c2, -mc1),
                                              fmaf(s_[mt][nt][3], c2, -mc1)));
            }
            uint32_t t0 = hadd2(hadd2(hadd2(pp[mt][0][0], pp[mt][1][0]),
                                      hadd2(pp[mt][2][0], pp[mt][3][0])),
                                hadd2(hadd2(pp[mt][4][0], pp[mt][5][0]),
                                      hadd2(pp[mt][6][0], pp[mt][7][0])));
            uint32_t t1 = hadd2(hadd2(hadd2(pp[mt][0][1], pp[mt][1][1]),
                                      hadd2(pp[mt][2][1], pp[mt][3][1])),
                                hadd2(hadd2(pp[mt][4][1], pp[mt][5][1]),
                                      hadd2(pp[mt][6][1], pp[mt][7][1])));
            float2 f0 = h2tof2(t0);
            float2 f1 = h2tof2(t1);
            float sum0 = f0.x + f0.y;
            float sum1 = f1.x + f1.y;
            sum0 += __shfl_xor_sync(0xffffffffu, sum0, 1);
            sum0 += __shfl_xor_sync(0xffffffffu, sum0, 2);
            sum1 += __shfl_xor_sync(0xffffffffu, sum1, 1);
            sum1 += __shfl_xor_sync(0xffffffffu, sum1, 2);

            lst[mt][0] = lst[mt][0] * al0 + sum0;  mst[mt][0] = mn0;
            lst[mt][1] = lst[mt][1] * al1 + sum1;  mst[mt][1] = mn1;
#pragma unroll
            for (int et = 0; et < 8; et++) {
                oacc[mt][et][0] *= al0; oacc[mt][et][1] *= al0;
                oacc[mt][et][2] *= al1; oacc[mt][et][3] *= al1;
            }
        }

#pragma unroll
        for (int j2 = 0; j2 < 4; j2++) {
            uint32_t pa[2][4];
#pragma unroll
            for (int mt = 0; mt < 2; mt++) {
                pa[mt][0] = pp[mt][2 * j2][0];
                pa[mt][1] = pp[mt][2 * j2][1];
                pa[mt][2] = pp[mt][2 * j2 + 1][0];
                pa[mt][3] = pp[mt][2 * j2 + 1][1];
            }
#pragma unroll
            for (int p = 0; p < 4; p++) {
                uint32_t r[4];
                int row = j2 * 16 + (lane & 7) + ((lane >> 3) & 1) * 8;
                int unit = p * 2 + (lane >> 4);
                ldmx4t(r, vb + sw128((uint32_t)(row << 7) + (uint32_t)(unit << 4)));
                uint32_t bf0[2] = { r[0], r[1] };
                uint32_t bf1[2] = { r[2], r[3] };
#pragma unroll
                for (int mt = 0; mt < 2; mt++) {
                    mma16(oacc[mt][2 * p],     pa[mt], bf0);
                    mma16(oacc[mt][2 * p + 1], pa[mt], bf1);
                }
            }
        }
        if (++buf == 3) buf = 0;
    }

    __half* Og = O + base + (size_t)m0 * 512;
#pragma unroll
    for (int mt = 0; mt < 2; mt++) {
        const float i0 = 1.f / lst[mt][0];
        const float i1 = 1.f / lst[mt][1];
        int r0 = w * 32 + mt * 16 + qr;
#pragma unroll
        for (int et = 0; et < 8; et++) {
            int c = et * 8 + qc * 2;
            *(uint32_t*)(Og + (size_t)r0 * 512 + c)       = packh2(oacc[mt][et][0] * i0, oacc[mt][et][1] * i0);
            *(uint32_t*)(Og + (size_t)(r0 + 8) * 512 + c) = packh2(oacc[mt][et][2] * i1, oacc[mt][et][3] * i1);
        }
    }
}

// ---------------------------------------------------------------------------
// Launch
// ---------------------------------------------------------------------------
extern "C" void kernel_launch(void* const* d_in, const int* in_sizes, int n_in,
                              void* d_out, int out_size)
{
    const float* x1 = (const float*)d_in[0];
    const float* x2 = (const float*)d_in[1];
    const float* r  = (const float*)d_in[2];
    const float* W1 = (const float*)d_in[3];
    const float* b1 = (const float*)d_in[4];
    const float* W2 = (const float*)d_in[5];
    const float* b2 = (const float*)d_in[6];
    const float* Wq = (const float*)d_in[7];
    const float* Wk = (const float*)d_in[8];
    const float* Wv = (const float*)d_in[9];
    const float* Wo = (const float*)d_in[10];
    float* out = (float*)d_out;

    __half *H1, *H2, *QH, *KH, *VH, *Ob;
    __half *x1h, *x2h, *rh, *W1t, *W2h, *Wqh, *Wkh, *Wvh, *Wot, *Wqc, *Wkc;
    float *bq, *bk, *zb;
    cudaGetSymbolAddress((void**)&H1,  g_H1);
    cudaGetSymbolAddress((void**)&H2,  g_H2);
    cudaGetSymbolAddress((void**)&QH,  g_QH);
    cudaGetSymbolAddress((void**)&KH,  g_KH);
    cudaGetSymbolAddress((void**)&VH,  g_VH);
    cudaGetSymbolAddress((void**)&Ob,  g_O);
    cudaGetSymbolAddress((void**)&x1h, g_x1h);
    cudaGetSymbolAddress((void**)&x2h, g_x2h);
    cudaGetSymbolAddress((void**)&rh,  g_rh);
    cudaGetSymbolAddress((void**)&W1t, g_W1t);
    cudaGetSymbolAddress((void**)&W2h, g_W2h);
    cudaGetSymbolAddress((void**)&Wqh, g_Wqh);
    cudaGetSymbolAddress((void**)&Wkh, g_Wkh);
    cudaGetSymbolAddress((void**)&Wvh, g_Wvh);
    cudaGetSymbolAddress((void**)&Wot, g_Wot);
    cudaGetSymbolAddress((void**)&Wqc, g_Wqc);
    cudaGetSymbolAddress((void**)&Wkc, g_Wkc);
    cudaGetSymbolAddress((void**)&bq,  g_bq);
    cudaGetSymbolAddress((void**)&bk,  g_bk);
    cudaGetSymbolAddress((void**)&zb,  g_zb);

    cudaFuncSetAttribute(flash_h, cudaFuncAttributeMaxDynamicSharedMemorySize, FL_SMEM);
    cudaFuncSetAttribute((const void*)gemm_hb<true,  true,  false>, cudaFuncAttributeMaxDynamicSharedMemorySize, GEMM_SMEM);
    cudaFuncSetAttribute((const void*)gemm_hb<false, true,  false>, cudaFuncAttributeMaxDynamicSharedMemorySize, GEMM_SMEM);
    cudaFuncSetAttribute((const void*)gemm_hb<false, false, false>, cudaFuncAttributeMaxDynamicSharedMemorySize, GEMM_SMEM);
    cudaFuncSetAttribute((const void*)gemm_hb<false, false, true >, cudaFuncAttributeMaxDynamicSharedMemorySize, GEMM_SMEM);

    // --- pre-pass ---
    prep_inputs<<<dim3(1024, 1, 3), 256>>>((const float4*)x1, (const float4*)x2, (const float4*)r,
                                           (uint4*)x1h, (uint4*)x2h, (uint4*)rh);
    prep_weights<<<dim3(128, 1, 6), 256>>>(W1, W2, Wq, Wk, Wv, Wo,
                                           W1t, W2h, Wqh, Wkh, Wvh, Wot);
    bias_comp<<<1024, 128>>>(Wq, Wk, b2, bq, bk);

    // --- weight composition: Wqc = Wq@W2^T, Wkc = Wk@W2^T  (512x512x512) ---
    gemm_hb<false, false, false><<<dim3(4, 4, 2), 256, GEMM_SMEM>>>(
        Wqh, Wkh, Wqh, W2h, W2h, W2h, nullptr, nullptr, nullptr,
        Wqc, Wkc, Wqc, 512, 512);

    // --- MLP layer 1 (x1 -> H1, x2 -> H2) ---
    gemm_hb<true, true, false><<<dim3(4, 128, 2), 256, GEMM_SMEM>>>(
        x1h, x2h, x1h, W1t, W1t, W1t, b1, b1, b1, H1, H2, H1, 128, 512);

    // --- fused projections: QH = H2@Wqc^T + bq, KH = H1@Wkc^T + bk, VH = r@Wv^T ---
    gemm_hb<false, true, false><<<dim3(4, 128, 3), 256, GEMM_SMEM>>>(
        H2, H1, rh, Wqc, Wkc, Wvh, bq, bk, zb, QH, KH, VH, 512, 512);

    // --- attention ---
    flash_h<<<dim3(16, 64), 128, FL_SMEM>>>(QH, KH, VH, Ob);

    // --- output projection (f32 out) ---
    gemm_hb<false, false, true><<<dim3(4, 128, 1), 256, GEMM_SMEM>>>(
        Ob, Ob, Ob, Wot, Wot, Wot, nullptr, nullptr, nullptr, out, out, out, 512, 512);
}